// round 4
// baseline (speedup 1.0000x reference)
#include <cuda_runtime.h>
#include <cuda_bf16.h>
#include <limits.h>

// Problem constants (from reference setup_inputs):
//   B=64 batches, K=16 candidates, L_cand=32, L_src=64, pad_id=0
#define B_SZ   64
#define K_SZ   16
#define LC_SZ  32
#define LS_SZ  64

#define FULL_MASK 0xFFFFFFFFu
#define HALF_MASK 0x0000FFFFu

// One CTA per batch, one warp per candidate k (16 warps = 512 threads).
// Phase A (all warps): dot[k] via candidate-broadcast SHFL loop, c2 via
//   match_any, distributed r2 partials; REDUX; lane0 -> smem; ONE barrier.
// Phase B (warp 0 only): scores, stable rank sort, scores_sorted, then warp 0
//   itself reloads the winning candidate's tokens (L1-hot line) and writes
//   tokens + length. Warps 1..15 exit at the barrier. No second barrier.
__global__ void __launch_bounds__(512, 2)
ngram_rerank_kernel(const int* __restrict__ cand,   // [B, K, LC]
                    const int* __restrict__ src,    // [B, LS]
                    float* __restrict__ out_f,      // full fp32 layout, or null
                    int*   __restrict__ out_i)      // tokens-only int32, or null
{
    const int b    = blockIdx.x;
    const int tid  = threadIdx.x;
    const int warp = tid >> 5;     // candidate index k
    const int lane = tid & 31;

    __shared__ int sm_dot[K_SZ];
    __shared__ int sm_c2[K_SZ];
    __shared__ int sm_r2p[K_SZ];

    // ---- coalesced loads ----
    const int* sb = src + b * LS_SZ;
    const int s0 = sb[lane];
    const int s1 = sb[lane + 32];
    const int t  = cand[b * (K_SZ * LC_SZ) + warp * LC_SZ + lane];

    // ---- dot[k]: broadcast candidate tokens, compare vs s0/s1 ----
    // pad candidates masked to -1 (never equals any src token >= 0)
    const int t_m = (t != 0) ? t : -1;
    int d = 0;
    #pragma unroll
    for (int i = 0; i < 32; i++) {
        const int cv = __shfl_sync(FULL_MASK, t_m, i);
        d += (cv == s0);
        d += (cv == s1);
    }

    // ---- ||c_k||^2 via match groups ----
    const unsigned mm = __match_any_sync(FULL_MASK, t);
    const int c2_val  = (t != 0) ? __popc(mm) : 0;

    // ---- r2 partial: this warp handles broadcast src positions {2w, 2w+1} ----
    // lane-side sentinels: unique negatives per position (pads match nothing)
    const int s0m = (s0 != 0) ? s0 : ~lane;          // in [-32, -1]
    const int s1m = (s1 != 0) ? s1 : ~(lane + 32);   // in [-64, -33]
    int a = 0;
    #pragma unroll
    for (int q = 0; q < 2; q++) {
        int cv0 = __shfl_sync(FULL_MASK, s0m, 2 * warp + q);
        int cv1 = __shfl_sync(FULL_MASK, s1m, 2 * warp + q);
        cv0 = (cv0 < 0) ? INT_MIN : cv0;   // broadcast-side pads match nothing
        cv1 = (cv1 < 0) ? INT_MIN : cv1;
        a += (cv0 == s0m) + (cv0 == s1m) + (cv1 == s0m) + (cv1 == s1m);
    }

    const int dot = __reduce_add_sync(FULL_MASK, d);
    const int c2  = __reduce_add_sync(FULL_MASK, c2_val);
    const int r2p = __reduce_add_sync(FULL_MASK, a);

    if (lane == 0) {
        sm_dot[warp] = dot;
        sm_c2[warp]  = c2;
        sm_r2p[warp] = r2p;
    }
    __syncthreads();

    if (warp != 0) return;   // warps 1..15 done

    // ---- warp 0 finishes alone ----
    int kwin_l = 0;
    if (lane < K_SZ) {
        const int r2 = __reduce_add_sync(HALF_MASK, sm_r2p[lane]);
        const float rn = __fsqrt_rn((float)r2);
        const float cn = __fsqrt_rn((float)sm_c2[lane]);
        const float si = __fsub_rn(1.0f,
            __fdiv_rn((float)sm_dot[lane], __fmul_rn(rn, cn)));

        // stable descending rank (matches jnp.argsort(-scores), stable)
        int rank = 0;
        #pragma unroll
        for (int j = 0; j < K_SZ; j++) {
            const float sj = __shfl_sync(HALF_MASK, si, j);
            rank += (sj > si) || (sj == si && j < lane);
        }
        if (out_f != nullptr)
            out_f[B_SZ * LC_SZ + B_SZ + b * K_SZ + rank] = si;  // scores_sorted

        const unsigned winb = __ballot_sync(HALF_MASK, rank == 0);
        kwin_l = __ffs(winb) - 1;
    }
    const int kwin = __shfl_sync(FULL_MASK, kwin_l, 0);

    // Winning candidate's tokens: same cache line warp kwin just read -> L1 hit.
    const int tw = cand[b * (K_SZ * LC_SZ) + kwin * LC_SZ + lane];
    const unsigned nb = __ballot_sync(FULL_MASK, tw != 0);

    if (out_f != nullptr) {
        out_f[b * LC_SZ + lane] = (float)tw;                    // tokens
        if (lane == 0)
            out_f[B_SZ * LC_SZ + b] = (float)__popc(nb);        // length
    } else {
        out_i[b * LC_SZ + lane] = tw;
    }
}

extern "C" void kernel_launch(void* const* d_in, const int* in_sizes, int n_in,
                              void* d_out, int out_size)
{
    // Identify tensors by element count (robust to scalar inputs in the list):
    //   candidates: 64*16*32 = 32768,  src_ids: 64*64 = 4096
    const int* cand = nullptr;
    const int* src  = nullptr;
    for (int i = 0; i < n_in; i++) {
        if (in_sizes[i] == B_SZ * K_SZ * LC_SZ) cand = (const int*)d_in[i];
        else if (in_sizes[i] == B_SZ * LS_SZ)   src  = (const int*)d_in[i];
    }

    if (out_size == B_SZ * LC_SZ) {
        ngram_rerank_kernel<<<B_SZ, 512>>>(cand, src, nullptr, (int*)d_out);
    } else {
        ngram_rerank_kernel<<<B_SZ, 512>>>(cand, src, (float*)d_out, nullptr);
    }
}